// round 7
// baseline (speedup 1.0000x reference)
#include <cuda_runtime.h>
#include <cstdint>

// Horizontal correlation cost volume via banded tf32 mma.sync GEMM.
// a,b: fp32 [B=8, C=128, H=192, W=256], D=40.
// out[bi, ctr, h, w] = sum_c a[bi,c,h,w] * bp[bi,c,h, ctr+w], bp left-padded by 40.
//
// Persistent CTAs: grid=304 (2/SM), CTA k processes rows k, k+304, ... (5-6 rows).
// The 4-stage cp.async ring streams a GLOBAL chunk index across rows, so reads
// for row r+1 are in flight during row r's tail compute and epilogue -> DRAM
// never drains at row boundaries (R6 showed 75% DRAM plateau = pipeline holes,
// not outstanding-bytes).
//
// Per row: 16 warps, warp = one 16-wide w tile; each computes the 7 n-tiles of 8
// its diagonal band touches (m16n8k8 tf32 mma, cvt.rna.tf32.f32 operands).
// Epilogue uses a dedicated staging buffer (not the ring), two ctr-halves
// (21+20 rows), conflict-free STS then coalesced float4 STG.

#define C_TOT   128
#define W_DIM   256
#define H_DIM   192
#define B_DIM   8
#define NROWS_T (B_DIM * H_DIM)    // 1536
#define NCTR    41
#define NT      512
#define GRID    304                // 2 CTAs x 152 SMs
#define CC      8                  // channels per chunk = K per mma step
#define NCHUNK  16                 // chunks per row
#define NSTAGE  4
#define PFD     3                  // prefetch distance

#define A_PITCH 264                // 256 data + 8 pad
#define B_PITCH 312                // 304 data (40 zero|256|8 zero) + 8 pad
#define STAGE_F (CC * (A_PITCH + B_PITCH))   // 4608 floats per stage
#define B_OFF   (CC * A_PITCH)               // 2112 floats
#define RING_F  (NSTAGE * STAGE_F)           // 18432 floats
#define OUT_PITCH 260
#define OUT_HALF_ROWS 21
#define SMEM_BYTES ((RING_F + OUT_HALF_ROWS * OUT_PITCH) * 4)   // 95568 B

__device__ __forceinline__ void cpasync16(uint32_t dst, const void* src) {
    asm volatile("cp.async.cg.shared.global [%0], [%1], 16;\n" :: "r"(dst), "l"(src));
}
__device__ __forceinline__ void cp_commit() {
    asm volatile("cp.async.commit_group;\n");
}
__device__ __forceinline__ void cp_wait2() {
    asm volatile("cp.async.wait_group 2;\n" ::: "memory");
}
__device__ __forceinline__ uint32_t to_tf32(float f) {
    uint32_t u;
    asm("cvt.rna.tf32.f32 %0, %1;" : "=r"(u) : "f"(f));
    return u;
}
__device__ __forceinline__ void mma_tf32(float& d0, float& d1, float& d2, float& d3,
                                         uint32_t a0, uint32_t a1, uint32_t a2, uint32_t a3,
                                         uint32_t b0, uint32_t b1) {
    asm volatile("mma.sync.aligned.m16n8k8.row.col.f32.tf32.tf32.f32 "
                 "{%0,%1,%2,%3}, {%4,%5,%6,%7}, {%8,%9}, {%0,%1,%2,%3};\n"
                 : "+f"(d0), "+f"(d1), "+f"(d2), "+f"(d3)
                 : "r"(a0), "r"(a1), "r"(a2), "r"(a3), "r"(b0), "r"(b1));
}

__global__ __launch_bounds__(NT, 2)
void corr_kernel(const float* __restrict__ A,
                 const float* __restrict__ B,
                 float* __restrict__ O)
{
    extern __shared__ __align__(16) float sm[];
    float* outs = sm + RING_F;                 // epilogue staging (separate)

    const int bid  = blockIdx.x;
    const int tid  = threadIdx.x;
    const int wid  = tid >> 5;
    const int lane = tid & 31;
    const int WB   = wid * 16;
    const int q    = lane & 3;
    const int r0   = lane >> 2;

    const uint32_t smb = (uint32_t)__cvta_generic_to_shared(sm);

    // rows handled by this CTA: bid, bid+GRID, ...  (5 or 6 rows)
    const int nrows = (NROWS_T - bid + GRID - 1) / GRID;
    const int tot   = nrows * NCHUNK;          // total chunks, global index g

    // ---- zero the permanent pad blocks of b rows in every stage (once) ----
    for (int t = tid; t < NSTAGE * CC * 12; t += NT) {
        int st = t / (CC * 12);
        int u  = t - st * (CC * 12);
        int c  = u / 12;
        int j  = u - c * 12;
        int blk = (j < 10) ? j : (64 + j);
        float4* p = (float4*)(sm + st * STAGE_F + B_OFF + c * B_PITCH) + blk;
        *p = make_float4(0.f, 0.f, 0.f, 0.f);
    }

    // fixed per-thread load coordinates
    const int pc   = tid >> 6;                 // channel within chunk (0..7)
    const int pblk = tid & 63;                 // float4 block (0..63)
    const uint32_t adst0 = smb + (pc * A_PITCH) * 4 + pblk * 16;
    const uint32_t bdst0 = smb + (B_OFF + pc * B_PITCH) * 4 + (pblk + 10) * 16;

    // prefetch global chunk g into ring stage st (row derived from g)
    auto prefetch = [&](int g, int st) {
        int ri   = g >> 4;                     // row index within this CTA
        int lc   = g & 15;                     // chunk within row
        int rowg = bid + ri * GRID;
        int bi   = rowg / H_DIM;
        int h    = rowg - bi * H_DIM;
        size_t off = ((size_t)(bi * C_TOT + lc * CC + pc) * H_DIM + h) * W_DIM
                     + pblk * 4;
        uint32_t so = (uint32_t)(st * STAGE_F * 4);
        cpasync16(adst0 + so, A + off);
        cpasync16(bdst0 + so, B + off);
        cp_commit();
    };

    float acc[7][4];
#pragma unroll
    for (int jt = 0; jt < 7; ++jt)
#pragma unroll
        for (int k = 0; k < 4; ++k) acc[jt][k] = 0.0f;

#pragma unroll
    for (int p = 0; p < PFD; ++p) prefetch(p, p);

    for (int g = 0; g < tot; ++g) {
        const int st = g & (NSTAGE - 1);
        cp_wait2();            // 2 newest groups may remain -> chunk g resident
        __syncthreads();       // all warps done with stage st's previous use

        if (g + PFD < tot) prefetch(g + PFD, (g + PFD) & (NSTAGE - 1));
        else               cp_commit();       // empty group keeps FIFO invariant

        const float* as = sm + st * STAGE_F;
        const float* bs = sm + st * STAGE_F + B_OFF;

        uint32_t a0 = to_tf32(as[q * A_PITCH + WB + r0]);
        uint32_t a1 = to_tf32(as[q * A_PITCH + WB + r0 + 8]);
        uint32_t a2 = to_tf32(as[(q + 4) * A_PITCH + WB + r0]);
        uint32_t a3 = to_tf32(as[(q + 4) * A_PITCH + WB + r0 + 8]);

#pragma unroll
        for (int jt = 0; jt < 7; ++jt) {
            int j = WB + jt * 8 + r0;
            uint32_t b0 = to_tf32(bs[q * B_PITCH + j]);
            uint32_t b1 = to_tf32(bs[(q + 4) * B_PITCH + j]);
            mma_tf32(acc[jt][0], acc[jt][1], acc[jt][2], acc[jt][3],
                     a0, a1, a2, a3, b0, b1);
        }

        // ---- row finished: epilogue (staging is separate from ring, so the
        //      3 in-flight prefetch groups for the next row keep DRAM busy) ----
        if ((g & 15) == 15) {
            int rowg = bid + (g >> 4) * GRID;
            int bi   = rowg / H_DIM;
            int h    = rowg - bi * H_DIM;

#pragma unroll
            for (int half = 0; half < 2; ++half) {
                const int cbase  = half ? OUT_HALF_ROWS : 0;            // 0 / 21
                const int ccount = half ? (NCTR - OUT_HALF_ROWS) : OUT_HALF_ROWS; // 20 / 21

                // band-extract this ctr half (warp-local, disjoint columns)
#pragma unroll
                for (int jt = 0; jt < 7; ++jt) {
                    int nb = jt * 8 + 2 * q;
                    int c00 = nb - r0;
                    int c10 = nb - (r0 + 8);
                    if (c00 >= cbase && c00 < cbase + ccount)
                        outs[(c00 - cbase) * OUT_PITCH + WB + r0] = acc[jt][0];
                    if (c00 + 1 >= cbase && c00 + 1 < cbase + ccount)
                        outs[(c00 + 1 - cbase) * OUT_PITCH + WB + r0] = acc[jt][1];
                    if (c10 >= cbase && c10 < cbase + ccount)
                        outs[(c10 - cbase) * OUT_PITCH + WB + r0 + 8] = acc[jt][2];
                    if (c10 + 1 >= cbase && c10 + 1 < cbase + ccount)
                        outs[(c10 + 1 - cbase) * OUT_PITCH + WB + r0 + 8] = acc[jt][3];
                }
                __syncthreads();

                // coalesced write-out of this half: ccount x 64 float4
                for (int idx = tid; idx < ccount * 64; idx += NT) {
                    int cr  = idx >> 6;
                    int blk = idx & 63;
                    float4 v = *(const float4*)(outs + cr * OUT_PITCH + blk * 4);
                    float* dst = O + (((size_t)bi * NCTR + cbase + cr) * H_DIM + h)
                                   * W_DIM + blk * 4;
                    *(float4*)dst = v;
                }
                __syncthreads();
            }

#pragma unroll
            for (int jt = 0; jt < 7; ++jt)
#pragma unroll
                for (int k = 0; k < 4; ++k) acc[jt][k] = 0.0f;
        }
    }
}

extern "C" void kernel_launch(void* const* d_in, const int* in_sizes, int n_in,
                              void* d_out, int out_size)
{
    const float* a = (const float*)d_in[0];
    const float* b = (const float*)d_in[1];
    float* out = (float*)d_out;

    cudaFuncSetAttribute(corr_kernel,
                         cudaFuncAttributeMaxDynamicSharedMemorySize, SMEM_BYTES);

    dim3 grid(GRID);            // persistent: 2 CTAs per SM
    dim3 block(NT);
    corr_kernel<<<grid, block, SMEM_BYTES>>>(a, b, out);
}

// round 8
// speedup vs baseline: 1.0321x; 1.0321x over previous
#include <cuda_runtime.h>
#include <cstdint>

// Horizontal correlation cost volume via banded tf32 mma.sync GEMM.
// a,b: fp32 [B=8, C=128, H=192, W=256], D=40.
// out[bi, ctr, h, w] = sum_c a[bi,c,h,w] * bp[bi,c,h, ctr+w], bp left-padded by 40.
//
// One CTA per (bi,h) row (R7 persistent variant regressed; reverted).
// 512 threads = 16 warps; warp = one 16-wide w tile computing the 7 n-tiles of
// 8 its diagonal band touches. m16n8k8 tf32 mma, cvt.rna.tf32.f32 operands.
//
// CC=16 channels per chunk (2 mma k-steps per barrier) halves the number of
// wait_group+syncthreads rounds per row vs the CC=8 version (R6: DRAM pinned
// ~75% with issue ~52% -> barrier quantization, not outstanding bytes).
// 3-stage cp.async ring, prefetch distance 2, wait_group 1: 2 x 36KB chunks in
// flight per CTA (~22MB chip-wide).
//
// Epilogue: band-extract into a 41x260 smem tile (reuses ring smem), then
// fully coalesced float4 stores.

#define C_TOT   128
#define W_DIM   256
#define H_DIM   192
#define B_DIM   8
#define NCTR    41
#define NT      512
#define CC      16                 // channels per chunk = 2 mma k-steps
#define NCHUNK  (C_TOT / CC)       // 8
#define NSTAGE  3
#define PFD     2                  // prefetch distance

#define A_PITCH 264                // 256 data + 8 pad
#define B_PITCH 312                // 304 data (40 zero|256|8 zero) + 8 pad
#define STAGE_F (CC * (A_PITCH + B_PITCH))   // 9216 floats per stage
#define B_OFF   (CC * A_PITCH)               // 4224 floats
#define OUT_PITCH 260
#define OUT_F   (NCTR * OUT_PITCH)           // 10660 floats (< STAGE_F*3)
#define RING_F  (NSTAGE * STAGE_F)           // 27648 floats
#define SMEM_BYTES (RING_F * 4)              // 110592 B

__device__ __forceinline__ void cpasync16(uint32_t dst, const void* src) {
    asm volatile("cp.async.cg.shared.global [%0], [%1], 16;\n" :: "r"(dst), "l"(src));
}
__device__ __forceinline__ void cp_commit() {
    asm volatile("cp.async.commit_group;\n");
}
__device__ __forceinline__ void cp_wait1() {
    asm volatile("cp.async.wait_group 1;\n" ::: "memory");
}
__device__ __forceinline__ uint32_t to_tf32(float f) {
    uint32_t u;
    asm("cvt.rna.tf32.f32 %0, %1;" : "=r"(u) : "f"(f));
    return u;
}
__device__ __forceinline__ void mma_tf32(float& d0, float& d1, float& d2, float& d3,
                                         uint32_t a0, uint32_t a1, uint32_t a2, uint32_t a3,
                                         uint32_t b0, uint32_t b1) {
    asm volatile("mma.sync.aligned.m16n8k8.row.col.f32.tf32.tf32.f32 "
                 "{%0,%1,%2,%3}, {%4,%5,%6,%7}, {%8,%9}, {%0,%1,%2,%3};\n"
                 : "+f"(d0), "+f"(d1), "+f"(d2), "+f"(d3)
                 : "r"(a0), "r"(a1), "r"(a2), "r"(a3), "r"(b0), "r"(b1));
}

__global__ __launch_bounds__(NT, 2)
void corr_kernel(const float* __restrict__ A,
                 const float* __restrict__ B,
                 float* __restrict__ O)
{
    extern __shared__ __align__(16) float sm[];

    const int row  = blockIdx.x;
    const int bi   = row / H_DIM;
    const int h    = row - bi * H_DIM;
    const int tid  = threadIdx.x;
    const int wid  = tid >> 5;
    const int lane = tid & 31;
    const int WB   = wid * 16;
    const int q    = lane & 3;
    const int r0   = lane >> 2;

    const size_t plane = (size_t)H_DIM * W_DIM;
    const float* Arow = A + ((size_t)bi * C_TOT * H_DIM + h) * W_DIM;
    const float* Brow = B + ((size_t)bi * C_TOT * H_DIM + h) * W_DIM;

    const uint32_t smb = (uint32_t)__cvta_generic_to_shared(sm);

    // ---- zero the permanent pad blocks of b rows in every stage (once) ----
    // b row float4 blocks {0..9, 74, 75} are pad; cp.async never writes them.
    for (int t = tid; t < NSTAGE * CC * 12; t += NT) {
        int st = t / (CC * 12);
        int u  = t - st * (CC * 12);
        int c  = u / 12;
        int j  = u - c * 12;
        int blk = (j < 10) ? j : (64 + j);     // 74, 75
        float4* p = (float4*)(sm + st * STAGE_F + B_OFF + c * B_PITCH) + blk;
        *p = make_float4(0.f, 0.f, 0.f, 0.f);
    }

    float acc[7][4];
#pragma unroll
    for (int jt = 0; jt < 7; ++jt)
#pragma unroll
        for (int k = 0; k < 4; ++k) acc[jt][k] = 0.0f;

    // fixed per-thread load coordinates: each thread copies 2 a-blocks + 2
    // b-blocks per chunk (CC*64 = 1024 blocks each, 512 threads)
    const int pc   = tid >> 6;                 // channel 0..7 (and +8)
    const int pblk = tid & 63;                 // float4 block 0..63
    const float* Asrc0 = Arow + (size_t)pc * plane + pblk * 4;
    const float* Bsrc0 = Brow + (size_t)pc * plane + pblk * 4;
    const size_t half  = (size_t)8 * plane;    // channel +8 offset in gmem
    const uint32_t adst0 = smb + (pc * A_PITCH) * 4 + pblk * 16;
    const uint32_t bdst0 = smb + (B_OFF + pc * B_PITCH) * 4 + (pblk + 10) * 16;
    const size_t chstep = (size_t)CC * plane;

    auto prefetch = [&](int ch, int st) {
        const size_t off = (size_t)ch * chstep;
        const uint32_t so = (uint32_t)(st * STAGE_F * 4);
        cpasync16(adst0 + so, Asrc0 + off);
        cpasync16(adst0 + so + 8 * A_PITCH * 4, Asrc0 + off + half);
        cpasync16(bdst0 + so, Bsrc0 + off);
        cpasync16(bdst0 + so + 8 * B_PITCH * 4, Bsrc0 + off + half);
        cp_commit();
    };

#pragma unroll
    for (int p = 0; p < PFD; ++p) prefetch(p, p);

    int st = 0;
    for (int ch = 0; ch < NCHUNK; ++ch) {
        cp_wait1();            // newest group may remain -> chunk ch resident
        __syncthreads();       // all warps done with stage st's previous use

        if (ch + PFD < NCHUNK) {
            int stn = st + PFD; if (stn >= NSTAGE) stn -= NSTAGE;
            prefetch(ch + PFD, stn);
        } else {
            cp_commit();       // empty group keeps FIFO invariant
        }

        const float* as = sm + st * STAGE_F;
        const float* bs = as + B_OFF;

#pragma unroll
        for (int ks = 0; ks < 2; ++ks) {       // two k8 steps per chunk
            const float* ak = as + (ks * 8) * A_PITCH;
            const float* bk = bs + (ks * 8) * B_PITCH;

            uint32_t a0 = to_tf32(ak[q * A_PITCH + WB + r0]);
            uint32_t a1 = to_tf32(ak[q * A_PITCH + WB + r0 + 8]);
            uint32_t a2 = to_tf32(ak[(q + 4) * A_PITCH + WB + r0]);
            uint32_t a3 = to_tf32(ak[(q + 4) * A_PITCH + WB + r0 + 8]);

#pragma unroll
            for (int jt = 0; jt < 7; ++jt) {
                int j = WB + jt * 8 + r0;
                uint32_t b0 = to_tf32(bk[q * B_PITCH + j]);
                uint32_t b1 = to_tf32(bk[(q + 4) * B_PITCH + j]);
                mma_tf32(acc[jt][0], acc[jt][1], acc[jt][2], acc[jt][3],
                         a0, a1, a2, a3, b0, b1);
            }
        }

        if (++st == NSTAGE) st = 0;
    }

    // ---- band extraction into smem: out_s[ctr][w] (reuses ring smem) ----
    __syncthreads();
#pragma unroll
    for (int jt = 0; jt < 7; ++jt) {
        int nb = jt * 8 + 2 * q;
        int ctr00 = nb - r0;
        int ctr10 = nb - (r0 + 8);
        if (ctr00 >= 0 && ctr00 <= 40)         sm[ctr00 * OUT_PITCH + WB + r0]           = acc[jt][0];
        if (ctr00 + 1 >= 0 && ctr00 + 1 <= 40) sm[(ctr00 + 1) * OUT_PITCH + WB + r0]     = acc[jt][1];
        if (ctr10 >= 0 && ctr10 <= 40)         sm[ctr10 * OUT_PITCH + WB + r0 + 8]       = acc[jt][2];
        if (ctr10 + 1 >= 0 && ctr10 + 1 <= 40) sm[(ctr10 + 1) * OUT_PITCH + WB + r0 + 8] = acc[jt][3];
    }
    __syncthreads();

    // ---- coalesced write-out: 41 x 64 float4 ----
    for (int idx = tid; idx < NCTR * 64; idx += NT) {
        int ctr = idx >> 6;
        int blk = idx & 63;
        float4 v = *(const float4*)(sm + ctr * OUT_PITCH + blk * 4);
        float* dst = O + (((size_t)bi * NCTR + ctr) * H_DIM + h) * W_DIM + blk * 4;
        *(float4*)dst = v;
    }
}

extern "C" void kernel_launch(void* const* d_in, const int* in_sizes, int n_in,
                              void* d_out, int out_size)
{
    const float* a = (const float*)d_in[0];
    const float* b = (const float*)d_in[1];
    float* out = (float*)d_out;

    cudaFuncSetAttribute(corr_kernel,
                         cudaFuncAttributeMaxDynamicSharedMemorySize, SMEM_BYTES);

    dim3 grid(B_DIM * H_DIM);   // 1536 CTAs, one per (batch, h) row
    dim3 block(NT);
    corr_kernel<<<grid, block, SMEM_BYTES>>>(a, b, out);
}

// round 10
// speedup vs baseline: 1.0502x; 1.0176x over previous
#include <cuda_runtime.h>
#include <cstdint>

// Horizontal correlation cost volume via banded tf32 mma.sync GEMM.
// a,b: fp32 [B=8, C=128, H=192, W=256], D=40.
// out[bi, ctr, h, w] = sum_c a[bi,c,h,w] * bp[bi,c,h, ctr+w], bp left-padded by 40.
//
// One CTA per (bi,h) row. 512 threads = 16 warps; warp = one 16-wide w tile
// computing the 7 n-tiles of 8 its diagonal band touches. m16n8k8 tf32 mma,
// cvt.rna.tf32.f32 operands.
//
// CC=16 channels per chunk (2 mma k-steps per barrier), 3-stage cp.async ring,
// prefetch distance 2. Chunk loop: sync (stage-reuse guard) -> prefetch next
// chunk -> wait_group 2 -> sync (visibility: wait_group only orders THIS
// thread's copies; the barrier after the wait publishes all threads' copies
// -- R9 omitted it and raced) -> compute.
//
// Epilogue: band-extract into a 41x260 smem tile (reuses ring smem), then
// coalesced float4 stores with .cs streaming hint.

#define C_TOT   128
#define W_DIM   256
#define H_DIM   192
#define B_DIM   8
#define NCTR    41
#define NT      512
#define CC      16                 // channels per chunk = 2 mma k-steps
#define NCHUNK  (C_TOT / CC)       // 8
#define NSTAGE  3
#define PFD     2                  // prefetch distance

#define A_PITCH 264                // 256 data + 8 pad
#define B_PITCH 312                // 304 data (40 zero|256|8 zero) + 8 pad
#define STAGE_F (CC * (A_PITCH + B_PITCH))   // 9216 floats per stage
#define B_OFF   (CC * A_PITCH)               // 4224 floats
#define OUT_PITCH 260
#define RING_F  (NSTAGE * STAGE_F)           // 27648 floats
#define SMEM_BYTES (RING_F * 4)              // 110592 B

__device__ __forceinline__ void cpasync16(uint32_t dst, const void* src) {
    asm volatile("cp.async.cg.shared.global [%0], [%1], 16;\n" :: "r"(dst), "l"(src));
}
__device__ __forceinline__ void cp_commit() {
    asm volatile("cp.async.commit_group;\n");
}
__device__ __forceinline__ void cp_wait2() {
    asm volatile("cp.async.wait_group 2;\n" ::: "memory");
}
__device__ __forceinline__ uint32_t to_tf32(float f) {
    uint32_t u;
    asm("cvt.rna.tf32.f32 %0, %1;" : "=r"(u) : "f"(f));
    return u;
}
__device__ __forceinline__ void mma_tf32(float& d0, float& d1, float& d2, float& d3,
                                         uint32_t a0, uint32_t a1, uint32_t a2, uint32_t a3,
                                         uint32_t b0, uint32_t b1) {
    asm volatile("mma.sync.aligned.m16n8k8.row.col.f32.tf32.tf32.f32 "
                 "{%0,%1,%2,%3}, {%4,%5,%6,%7}, {%8,%9}, {%0,%1,%2,%3};\n"
                 : "+f"(d0), "+f"(d1), "+f"(d2), "+f"(d3)
                 : "r"(a0), "r"(a1), "r"(a2), "r"(a3), "r"(b0), "r"(b1));
}
__device__ __forceinline__ void stg_cs_v4(float* p, float x, float y, float z, float w) {
    asm volatile("st.global.cs.v4.f32 [%0], {%1, %2, %3, %4};\n"
                 :: "l"(p), "f"(x), "f"(y), "f"(z), "f"(w) : "memory");
}

__global__ __launch_bounds__(NT, 2)
void corr_kernel(const float* __restrict__ A,
                 const float* __restrict__ B,
                 float* __restrict__ O)
{
    extern __shared__ __align__(16) float sm[];

    const int row  = blockIdx.x;
    const int bi   = row / H_DIM;
    const int h    = row - bi * H_DIM;
    const int tid  = threadIdx.x;
    const int wid  = tid >> 5;
    const int lane = tid & 31;
    const int WB   = wid * 16;
    const int q    = lane & 3;
    const int r0   = lane >> 2;

    const size_t plane = (size_t)H_DIM * W_DIM;
    const float* Arow = A + ((size_t)bi * C_TOT * H_DIM + h) * W_DIM;
    const float* Brow = B + ((size_t)bi * C_TOT * H_DIM + h) * W_DIM;

    const uint32_t smb = (uint32_t)__cvta_generic_to_shared(sm);

    // ---- zero the permanent pad blocks of b rows in every stage (once) ----
    for (int t = tid; t < NSTAGE * CC * 12; t += NT) {
        int st = t / (CC * 12);
        int u  = t - st * (CC * 12);
        int c  = u / 12;
        int j  = u - c * 12;
        int blk = (j < 10) ? j : (64 + j);     // 74, 75
        float4* p = (float4*)(sm + st * STAGE_F + B_OFF + c * B_PITCH) + blk;
        *p = make_float4(0.f, 0.f, 0.f, 0.f);
    }

    float acc[7][4];
#pragma unroll
    for (int jt = 0; jt < 7; ++jt)
#pragma unroll
        for (int k = 0; k < 4; ++k) acc[jt][k] = 0.0f;

    // fixed per-thread load coordinates: 2 a-blocks + 2 b-blocks per chunk
    const int pc   = tid >> 6;                 // channel 0..7 (and +8)
    const int pblk = tid & 63;                 // float4 block 0..63
    const float* Asrc0 = Arow + (size_t)pc * plane + pblk * 4;
    const float* Bsrc0 = Brow + (size_t)pc * plane + pblk * 4;
    const size_t half  = (size_t)8 * plane;
    const uint32_t adst0 = smb + (pc * A_PITCH) * 4 + pblk * 16;
    const uint32_t bdst0 = smb + (B_OFF + pc * B_PITCH) * 4 + (pblk + 10) * 16;
    const size_t chstep = (size_t)CC * plane;

    auto prefetch = [&](int ch, int st) {
        const size_t off = (size_t)ch * chstep;
        const uint32_t so = (uint32_t)(st * STAGE_F * 4);
        cpasync16(adst0 + so, Asrc0 + off);
        cpasync16(adst0 + so + 8 * A_PITCH * 4, Asrc0 + off + half);
        cpasync16(bdst0 + so, Bsrc0 + off);
        cpasync16(bdst0 + so + 8 * B_PITCH * 4, Bsrc0 + off + half);
        cp_commit();
    };

#pragma unroll
    for (int p = 0; p < PFD; ++p) prefetch(p, p);

    int st = 0;
    for (int ch = 0; ch < NCHUNK; ++ch) {
        // stage-reuse guard: all warps finished chunk ch-1 (same stage that
        // chunk ch+PFD is about to overwrite).
        __syncthreads();

        if (ch + PFD < NCHUNK) {
            int stn = st + PFD; if (stn >= NSTAGE) stn -= NSTAGE;
            prefetch(ch + PFD, stn);           // issue reads BEFORE blocking
        } else {
            cp_commit();                       // empty group keeps FIFO invariant
        }

        cp_wait2();        // this thread's copies for chunk ch complete
        __syncthreads();   // publish ALL threads' copies (required: wait_group
                           // is per-thread; omitting this barrier raced in R9)

        const float* as = sm + st * STAGE_F;
        const float* bs = as + B_OFF;

#pragma unroll
        for (int ks = 0; ks < 2; ++ks) {       // two k8 steps per chunk
            const float* ak = as + (ks * 8) * A_PITCH;
            const float* bk = bs + (ks * 8) * B_PITCH;

            uint32_t a0 = to_tf32(ak[q * A_PITCH + WB + r0]);
            uint32_t a1 = to_tf32(ak[q * A_PITCH + WB + r0 + 8]);
            uint32_t a2 = to_tf32(ak[(q + 4) * A_PITCH + WB + r0]);
            uint32_t a3 = to_tf32(ak[(q + 4) * A_PITCH + WB + r0 + 8]);

#pragma unroll
            for (int jt = 0; jt < 7; ++jt) {
                int j = WB + jt * 8 + r0;
                uint32_t b0 = to_tf32(bk[q * B_PITCH + j]);
                uint32_t b1 = to_tf32(bk[(q + 4) * B_PITCH + j]);
                mma_tf32(acc[jt][0], acc[jt][1], acc[jt][2], acc[jt][3],
                         a0, a1, a2, a3, b0, b1);
            }
        }

        if (++st == NSTAGE) st = 0;
    }

    // ---- band extraction into smem: out_s[ctr][w] (reuses ring smem) ----
    __syncthreads();
#pragma unroll
    for (int jt = 0; jt < 7; ++jt) {
        int nb = jt * 8 + 2 * q;
        int ctr00 = nb - r0;
        int ctr10 = nb - (r0 + 8);
        if (ctr00 >= 0 && ctr00 <= 40)         sm[ctr00 * OUT_PITCH + WB + r0]           = acc[jt][0];
        if (ctr00 + 1 >= 0 && ctr00 + 1 <= 40) sm[(ctr00 + 1) * OUT_PITCH + WB + r0]     = acc[jt][1];
        if (ctr10 >= 0 && ctr10 <= 40)         sm[ctr10 * OUT_PITCH + WB + r0 + 8]       = acc[jt][2];
        if (ctr10 + 1 >= 0 && ctr10 + 1 <= 40) sm[(ctr10 + 1) * OUT_PITCH + WB + r0 + 8] = acc[jt][3];
    }
    __syncthreads();

    // ---- write-out: 41 x 64 float4, streaming (.cs) stores ----
    for (int idx = tid; idx < NCTR * 64; idx += NT) {
        int ctr = idx >> 6;
        int blk = idx & 63;
        const float* s = sm + ctr * OUT_PITCH + blk * 4;
        float* dst = O + (((size_t)bi * NCTR + ctr) * H_DIM + h) * W_DIM + blk * 4;
        stg_cs_v4(dst, s[0], s[1], s[2], s[3]);
    }
}

extern "C" void kernel_launch(void* const* d_in, const int* in_sizes, int n_in,
                              void* d_out, int out_size)
{
    const float* a = (const float*)d_in[0];
    const float* b = (const float*)d_in[1];
    float* out = (float*)d_out;

    cudaFuncSetAttribute(corr_kernel,
                         cudaFuncAttributeMaxDynamicSharedMemorySize, SMEM_BYTES);

    dim3 grid(B_DIM * H_DIM);   // 1536 CTAs, one per (batch, h) row
    dim3 block(NT);
    corr_kernel<<<grid, block, SMEM_BYTES>>>(a, b, out);
}

// round 11
// speedup vs baseline: 1.0537x; 1.0034x over previous
#include <cuda_runtime.h>
#include <cstdint>

// Horizontal correlation cost volume via banded tf32 mma.sync GEMM.
// a,b: fp32 [B=8, C=128, H=192, W=256], D=40.
// out[bi, ctr, h, w] = sum_c a[bi,c,h,w] * bp[bi,c,h, ctr+w], bp left-padded by 40.
//
// One CTA per (bi,h) row. 512 threads = 16 warps; warp = one 16-wide w tile
// computing the 7 n-tiles of 8 its diagonal band touches. m16n8k8 tf32 mma,
// cvt.rna.tf32.f32 operands.
//
// CC=8 / NSTAGE=6 / PFD=4 single-barrier pipeline:
//   per chunk: prefetch(ch+4) -> cp.async.wait_group 4 -> __syncthreads -> compute
// With NSTAGE = PFD+2, the stage overwritten by prefetch at iter ch was last
// read at compute(ch-2); barrier(ch-1) already orders that, so no separate
// reuse-guard barrier is needed (R10 paid 2 barriers/chunk with NSTAGE=PFD+1).
// Reads are issued BEFORE blocking each iteration; 4 chunks (72KB/CTA,
// ~22MB chip-wide) in flight after each wait.
//
// Epilogue: band-extract into a 41x260 smem tile (reuses ring smem), then
// coalesced float4 stores with .cs streaming hint.

#define C_TOT   128
#define W_DIM   256
#define H_DIM   192
#define B_DIM   8
#define NCTR    41
#define NT      512
#define CC      8                  // channels per chunk = 1 mma k-step
#define NCHUNK  (C_TOT / CC)       // 16
#define NSTAGE  6
#define PFD     4                  // prefetch distance

#define A_PITCH 264                // 256 data + 8 pad
#define B_PITCH 312                // 304 data (40 zero|256|8 zero) + 8 pad
#define STAGE_F (CC * (A_PITCH + B_PITCH))   // 4608 floats per stage
#define B_OFF   (CC * A_PITCH)               // 2112 floats
#define OUT_PITCH 260
#define RING_F  (NSTAGE * STAGE_F)           // 27648 floats
#define SMEM_BYTES (RING_F * 4)              // 110592 B (> 41*260*4 = 42640)

__device__ __forceinline__ void cpasync16(uint32_t dst, const void* src) {
    asm volatile("cp.async.cg.shared.global [%0], [%1], 16;\n" :: "r"(dst), "l"(src));
}
__device__ __forceinline__ void cp_commit() {
    asm volatile("cp.async.commit_group;\n");
}
__device__ __forceinline__ void cp_wait4() {
    asm volatile("cp.async.wait_group 4;\n" ::: "memory");
}
__device__ __forceinline__ uint32_t to_tf32(float f) {
    uint32_t u;
    asm("cvt.rna.tf32.f32 %0, %1;" : "=r"(u) : "f"(f));
    return u;
}
__device__ __forceinline__ void mma_tf32(float& d0, float& d1, float& d2, float& d3,
                                         uint32_t a0, uint32_t a1, uint32_t a2, uint32_t a3,
                                         uint32_t b0, uint32_t b1) {
    asm volatile("mma.sync.aligned.m16n8k8.row.col.f32.tf32.tf32.f32 "
                 "{%0,%1,%2,%3}, {%4,%5,%6,%7}, {%8,%9}, {%0,%1,%2,%3};\n"
                 : "+f"(d0), "+f"(d1), "+f"(d2), "+f"(d3)
                 : "r"(a0), "r"(a1), "r"(a2), "r"(a3), "r"(b0), "r"(b1));
}
__device__ __forceinline__ void stg_cs_v4(float* p, float x, float y, float z, float w) {
    asm volatile("st.global.cs.v4.f32 [%0], {%1, %2, %3, %4};\n"
                 :: "l"(p), "f"(x), "f"(y), "f"(z), "f"(w) : "memory");
}

__global__ __launch_bounds__(NT, 2)
void corr_kernel(const float* __restrict__ A,
                 const float* __restrict__ B,
                 float* __restrict__ O)
{
    extern __shared__ __align__(16) float sm[];

    const int row  = blockIdx.x;
    const int bi   = row / H_DIM;
    const int h    = row - bi * H_DIM;
    const int tid  = threadIdx.x;
    const int wid  = tid >> 5;
    const int lane = tid & 31;
    const int WB   = wid * 16;
    const int q    = lane & 3;
    const int r0   = lane >> 2;

    const size_t plane = (size_t)H_DIM * W_DIM;
    const float* Arow = A + ((size_t)bi * C_TOT * H_DIM + h) * W_DIM;
    const float* Brow = B + ((size_t)bi * C_TOT * H_DIM + h) * W_DIM;

    const uint32_t smb = (uint32_t)__cvta_generic_to_shared(sm);

    // ---- zero the permanent pad blocks of b rows in every stage (once) ----
    // b row float4 blocks {0..9, 74, 75} are pad; cp.async never writes them.
    for (int t = tid; t < NSTAGE * CC * 12; t += NT) {
        int st = t / (CC * 12);
        int u  = t - st * (CC * 12);
        int c  = u / 12;
        int j  = u - c * 12;
        int blk = (j < 10) ? j : (64 + j);     // 74, 75
        float4* p = (float4*)(sm + st * STAGE_F + B_OFF + c * B_PITCH) + blk;
        *p = make_float4(0.f, 0.f, 0.f, 0.f);
    }

    float acc[7][4];
#pragma unroll
    for (int jt = 0; jt < 7; ++jt)
#pragma unroll
        for (int k = 0; k < 4; ++k) acc[jt][k] = 0.0f;

    // fixed per-thread load coordinates: 1 a-block + 1 b-block per chunk
    const int pc   = tid >> 6;                 // channel within chunk (0..7)
    const int pblk = tid & 63;                 // float4 block (0..63)
    const float* Asrc0 = Arow + (size_t)pc * plane + pblk * 4;
    const float* Bsrc0 = Brow + (size_t)pc * plane + pblk * 4;
    const uint32_t adst0 = smb + (pc * A_PITCH) * 4 + pblk * 16;
    const uint32_t bdst0 = smb + (B_OFF + pc * B_PITCH) * 4 + (pblk + 10) * 16;
    const size_t chstep = (size_t)CC * plane;

    auto prefetch = [&](int ch, int st) {
        const size_t off = (size_t)ch * chstep;
        const uint32_t so = (uint32_t)(st * STAGE_F * 4);
        cpasync16(adst0 + so, Asrc0 + off);
        cpasync16(bdst0 + so, Bsrc0 + off);
        cp_commit();
    };

    // initial barrier: pad-zero writes must be visible before any compute
    // (folded into the pipeline's first visibility barrier below — but the
    // pads are read in chunk 0, whose barrier comes after prefetch(4); the
    // zero-writes above are plain STS, ordered by that same __syncthreads.)

#pragma unroll
    for (int p = 0; p < PFD; ++p) prefetch(p, p);

    int st = 0;
    for (int ch = 0; ch < NCHUNK; ++ch) {
        // prefetch FIRST: stage (st+PFD)%NSTAGE was last read at compute(ch-2),
        // already ordered by barrier(ch-1) since NSTAGE = PFD+2.
        if (ch + PFD < NCHUNK) {
            int stn = st + PFD; if (stn >= NSTAGE) stn -= NSTAGE;
            prefetch(ch + PFD, stn);
        } else {
            cp_commit();                       // empty group keeps FIFO invariant
        }

        cp_wait4();        // this thread's copies for chunk ch complete
        __syncthreads();   // publish all threads' copies (single barrier/chunk)

        const float* as = sm + st * STAGE_F;
        const float* bs = as + B_OFF;

        uint32_t a0 = to_tf32(as[q * A_PITCH + WB + r0]);
        uint32_t a1 = to_tf32(as[q * A_PITCH + WB + r0 + 8]);
        uint32_t a2 = to_tf32(as[(q + 4) * A_PITCH + WB + r0]);
        uint32_t a3 = to_tf32(as[(q + 4) * A_PITCH + WB + r0 + 8]);

#pragma unroll
        for (int jt = 0; jt < 7; ++jt) {
            int j = WB + jt * 8 + r0;
            uint32_t b0 = to_tf32(bs[q * B_PITCH + j]);
            uint32_t b1 = to_tf32(bs[(q + 4) * B_PITCH + j]);
            mma_tf32(acc[jt][0], acc[jt][1], acc[jt][2], acc[jt][3],
                     a0, a1, a2, a3, b0, b1);
        }

        if (++st == NSTAGE) st = 0;
    }

    // ---- band extraction into smem: out_s[ctr][w] (reuses ring smem) ----
    __syncthreads();
#pragma unroll
    for (int jt = 0; jt < 7; ++jt) {
        int nb = jt * 8 + 2 * q;
        int ctr00 = nb - r0;
        int ctr10 = nb - (r0 + 8);
        if (ctr00 >= 0 && ctr00 <= 40)         sm[ctr00 * OUT_PITCH + WB + r0]           = acc[jt][0];
        if (ctr00 + 1 >= 0 && ctr00 + 1 <= 40) sm[(ctr00 + 1) * OUT_PITCH + WB + r0]     = acc[jt][1];
        if (ctr10 >= 0 && ctr10 <= 40)         sm[ctr10 * OUT_PITCH + WB + r0 + 8]       = acc[jt][2];
        if (ctr10 + 1 >= 0 && ctr10 + 1 <= 40) sm[(ctr10 + 1) * OUT_PITCH + WB + r0 + 8] = acc[jt][3];
    }
    __syncthreads();

    // ---- write-out: 41 x 64 float4, streaming (.cs) stores ----
    for (int idx = tid; idx < NCTR * 64; idx += NT) {
        int ctr = idx >> 6;
        int blk = idx & 63;
        const float* s = sm + ctr * OUT_PITCH + blk * 4;
        float* dst = O + (((size_t)bi * NCTR + ctr) * H_DIM + h) * W_DIM + blk * 4;
        stg_cs_v4(dst, s[0], s[1], s[2], s[3]);
    }
}

extern "C" void kernel_launch(void* const* d_in, const int* in_sizes, int n_in,
                              void* d_out, int out_size)
{
    const float* a = (const float*)d_in[0];
    const float* b = (const float*)d_in[1];
    float* out = (float*)d_out;

    cudaFuncSetAttribute(corr_kernel,
                         cudaFuncAttributeMaxDynamicSharedMemorySize, SMEM_BYTES);

    dim3 grid(B_DIM * H_DIM);   // 1536 CTAs, one per (batch, h) row
    dim3 block(NT);
    corr_kernel<<<grid, block, SMEM_BYTES>>>(a, b, out);
}

// round 12
// speedup vs baseline: 1.0590x; 1.0051x over previous
#include <cuda_runtime.h>
#include <cstdint>

// Horizontal correlation cost volume via banded tf32 mma.sync GEMM.
// a,b: fp32 [B=8, C=128, H=192, W=256], D=40.
// out[bi, ctr, h, w] = sum_c a[bi,c,h,w] * bp[bi,c,h, ctr+w], bp left-padded by 40.
//
// 4 CTAs/SM x 256 threads: each CTA owns HALF a (bi,h) row (128 w's), grid=3072.
// Doubles the number of independent barrier/cp.async domains per SM vs the
// 512-thread full-row version (R11: DRAM pinned 77% -- barrier-domain
// granularity, not pipeline schedule). Costs +4.5% b traffic (40-float window
// overlap between halves).
//
// 8 warps, warp = one 16-wide w tile; 7 n-tiles of 8 per warp (diagonal band).
// m16n8k8 tf32 mma, cvt.rna.tf32.f32 operands.
// CC=8 / NSTAGE=5 / PFD=3 single-barrier pipeline:
//   per chunk: prefetch(ch+3) -> cp.async.wait_group 3 -> __syncthreads -> compute
// (stage overwritten at iter ch was last read at compute(ch-2), ordered by
//  barrier(ch-1) since NSTAGE = PFD+2).
//
// Pitches: A_PITCH=136, B_PITCH=168, both == 8 (mod 32) -> fragment LDS banks
// are 8q+r0, conflict-free. Half-1's b window starts at b float 88 = float4
// block 22 (aligned). Only half-0 has permanent zero pad blocks (l<10).
//
// Epilogue: band-extract into a 41x132 smem tile (reuses ring smem), then
// coalesced float4 stores with .cs streaming hint.

#define C_TOT   128
#define W_DIM   256
#define H_DIM   192
#define B_DIM   8
#define NCTR    41
#define NT      256
#define CC      8                  // channels per chunk = 1 mma k-step
#define NCHUNK  (C_TOT / CC)       // 16
#define NSTAGE  5
#define PFD     3                  // prefetch distance

#define A_PITCH 136                // 128 data + 8 pad   (136 mod 32 = 8)
#define B_PITCH 168                // 168 window floats  (168 mod 32 = 8)
#define BBLKS   42                 // 168/4 float4 blocks per b channel row
#define STAGE_F (CC * (A_PITCH + B_PITCH))   // 2432 floats per stage
#define B_OFF   (CC * A_PITCH)               // 1088 floats
#define OUT_PITCH 132                        // 132 mod 32 = 4 (as before)
#define RING_F  (NSTAGE * STAGE_F)           // 12160 floats
#define SMEM_BYTES (RING_F * 4)              // 48640 B (> 41*132*4 = 21648)

__device__ __forceinline__ void cpasync16(uint32_t dst, const void* src) {
    asm volatile("cp.async.cg.shared.global [%0], [%1], 16;\n" :: "r"(dst), "l"(src));
}
__device__ __forceinline__ void cp_commit() {
    asm volatile("cp.async.commit_group;\n");
}
__device__ __forceinline__ void cp_wait3() {
    asm volatile("cp.async.wait_group 3;\n" ::: "memory");
}
__device__ __forceinline__ uint32_t to_tf32(float f) {
    uint32_t u;
    asm("cvt.rna.tf32.f32 %0, %1;" : "=r"(u) : "f"(f));
    return u;
}
__device__ __forceinline__ void mma_tf32(float& d0, float& d1, float& d2, float& d3,
                                         uint32_t a0, uint32_t a1, uint32_t a2, uint32_t a3,
                                         uint32_t b0, uint32_t b1) {
    asm volatile("mma.sync.aligned.m16n8k8.row.col.f32.tf32.tf32.f32 "
                 "{%0,%1,%2,%3}, {%4,%5,%6,%7}, {%8,%9}, {%0,%1,%2,%3};\n"
                 : "+f"(d0), "+f"(d1), "+f"(d2), "+f"(d3)
                 : "r"(a0), "r"(a1), "r"(a2), "r"(a3), "r"(b0), "r"(b1));
}
__device__ __forceinline__ void stg_cs_v4(float* p, float x, float y, float z, float w) {
    asm volatile("st.global.cs.v4.f32 [%0], {%1, %2, %3, %4};\n"
                 :: "l"(p), "f"(x), "f"(y), "f"(z), "f"(w) : "memory");
}

__global__ __launch_bounds__(NT, 4)
void corr_kernel(const float* __restrict__ A,
                 const float* __restrict__ B,
                 float* __restrict__ O)
{
    extern __shared__ __align__(16) float sm[];

    const int bidx = blockIdx.x;
    const int row  = bidx >> 1;               // (bi,h) row
    const int half = bidx & 1;                 // which w-half
    const int bi   = row / H_DIM;
    const int h    = row - bi * H_DIM;
    const int hb   = half * 128;               // w base of this CTA

    const int tid  = threadIdx.x;
    const int wid  = tid >> 5;                 // 0..7 -> local w tile
    const int lane = tid & 31;
    const int WL   = wid * 16;                 // local w base of this warp
    const int q    = lane & 3;
    const int r0   = lane >> 2;

    const size_t plane = (size_t)H_DIM * W_DIM;
    const float* Arow = A + ((size_t)bi * C_TOT * H_DIM + h) * W_DIM;
    const float* Brow = B + ((size_t)bi * C_TOT * H_DIM + h) * W_DIM;

    const uint32_t smb = (uint32_t)__cvta_generic_to_shared(sm);

    // ---- half 0: zero the 10 permanent pad blocks per b channel per stage ----
    if (half == 0) {
        for (int t = tid; t < NSTAGE * CC * 10; t += NT) {
            int st = t / (CC * 10);
            int u  = t - st * (CC * 10);
            int c  = u / 10;
            int l  = u - c * 10;               // local block 0..9
            float4* p = (float4*)(sm + st * STAGE_F + B_OFF + c * B_PITCH) + l;
            *p = make_float4(0.f, 0.f, 0.f, 0.f);
        }
    }

    float acc[7][4];
#pragma unroll
    for (int jt = 0; jt < 7; ++jt)
#pragma unroll
        for (int k = 0; k < 4; ++k) acc[jt][k] = 0.0f;

    // b source block base: local block l holds bp[hb + 4l .. hb+4l+4) =
    // b[hb + 4l - 40 ...] -> b block (hb/4) + l - 10. Valid iff >= 0.
    const int bsrc_base = (hb >> 2) - 10;

    auto prefetch = [&](int ch, int st) {
        const float* Ab = Arow + (size_t)ch * CC * plane;
        const float* Bb = Brow + (size_t)ch * CC * plane;
        const uint32_t so = (uint32_t)(st * STAGE_F * 4);
        {   // a: 8 ch x 32 blocks = 256, one per thread
            int c = tid >> 5, blk = tid & 31;
            uint32_t dst = smb + so + (c * A_PITCH) * 4 + blk * 16;
            cpasync16(dst, Ab + (size_t)c * plane + hb + blk * 4);
        }
        // b: 8 ch x 42 blocks = 336
#pragma unroll
        for (int idx = tid; idx < CC * BBLKS; idx += NT) {
            int c = idx / BBLKS;
            int l = idx - c * BBLKS;
            int g = bsrc_base + l;             // source b block
            if (g >= 0) {
                uint32_t dst = smb + so + (B_OFF + c * B_PITCH) * 4 + l * 16;
                cpasync16(dst, Bb + (size_t)c * plane + g * 4);
            }
        }
        cp_commit();
    };

#pragma unroll
    for (int p = 0; p < PFD; ++p) prefetch(p, p);

    int st = 0;
    for (int ch = 0; ch < NCHUNK; ++ch) {
        // prefetch FIRST: stage (st+PFD)%NSTAGE last read at compute(ch-2),
        // ordered by barrier(ch-1) since NSTAGE = PFD+2.
        if (ch + PFD < NCHUNK) {
            int stn = st + PFD; if (stn >= NSTAGE) stn -= NSTAGE;
            prefetch(ch + PFD, stn);
        } else {
            cp_commit();                       // empty group keeps FIFO invariant
        }

        cp_wait3();        // this thread's copies for chunk ch complete
        __syncthreads();   // publish all threads' copies

        const float* as = sm + st * STAGE_F;
        const float* bs = as + B_OFF;

        uint32_t a0 = to_tf32(as[q * A_PITCH + WL + r0]);
        uint32_t a1 = to_tf32(as[q * A_PITCH + WL + r0 + 8]);
        uint32_t a2 = to_tf32(as[(q + 4) * A_PITCH + WL + r0]);
        uint32_t a3 = to_tf32(as[(q + 4) * A_PITCH + WL + r0 + 8]);

#pragma unroll
        for (int jt = 0; jt < 7; ++jt) {
            int j = WL + jt * 8 + r0;          // local bp index 0..167
            uint32_t b0 = to_tf32(bs[q * B_PITCH + j]);
            uint32_t b1 = to_tf32(bs[(q + 4) * B_PITCH + j]);
            mma_tf32(acc[jt][0], acc[jt][1], acc[jt][2], acc[jt][3],
                     a0, a1, a2, a3, b0, b1);
        }

        if (++st == NSTAGE) st = 0;
    }

    // ---- band extraction into smem: out_s[ctr][w_local] (reuses ring smem) ----
    __syncthreads();
#pragma unroll
    for (int jt = 0; jt < 7; ++jt) {
        int nb = jt * 8 + 2 * q;
        int ctr00 = nb - r0;
        int ctr10 = nb - (r0 + 8);
        if (ctr00 >= 0 && ctr00 <= 40)         sm[ctr00 * OUT_PITCH + WL + r0]           = acc[jt][0];
        if (ctr00 + 1 >= 0 && ctr00 + 1 <= 40) sm[(ctr00 + 1) * OUT_PITCH + WL + r0]     = acc[jt][1];
        if (ctr10 >= 0 && ctr10 <= 40)         sm[ctr10 * OUT_PITCH + WL + r0 + 8]       = acc[jt][2];
        if (ctr10 + 1 >= 0 && ctr10 + 1 <= 40) sm[(ctr10 + 1) * OUT_PITCH + WL + r0 + 8] = acc[jt][3];
    }
    __syncthreads();

    // ---- write-out: 41 x 32 float4, streaming (.cs) stores ----
    for (int idx = tid; idx < NCTR * 32; idx += NT) {
        int ctr = idx >> 5;
        int blk = idx & 31;
        const float* s = sm + ctr * OUT_PITCH + blk * 4;
        float* dst = O + (((size_t)bi * NCTR + ctr) * H_DIM + h) * W_DIM + hb + blk * 4;
        stg_cs_v4(dst, s[0], s[1], s[2], s[3]);
    }
}

extern "C" void kernel_launch(void* const* d_in, const int* in_sizes, int n_in,
                              void* d_out, int out_size)
{
    const float* a = (const float*)d_in[0];
    const float* b = (const float*)d_in[1];
    float* out = (float*)d_out;

    cudaFuncSetAttribute(corr_kernel,
                         cudaFuncAttributeMaxDynamicSharedMemorySize, SMEM_BYTES);

    dim3 grid(B_DIM * H_DIM * 2);   // 3072 CTAs, one per (batch, h, w-half)
    dim3 block(NT);
    corr_kernel<<<grid, block, SMEM_BYTES>>>(a, b, out);
}

// round 13
// speedup vs baseline: 1.0823x; 1.0220x over previous
#include <cuda_runtime.h>
#include <cstdint>

// Horizontal correlation cost volume via banded tf32 mma.sync GEMM.
// a,b: fp32 [B=8, C=128, H=192, W=256], D=40.
// out[bi, ctr, h, w] = sum_c a[bi,c,h,w] * bp[bi,c,h, ctr+w], bp left-padded by 40.
//
// 4 CTAs/SM x 256 threads: each CTA owns HALF a (bi,h) row (128 w's), grid=3072.
// 8 warps, warp = one 16-wide w tile; 7 n-tiles of 8 per warp (diagonal band).
// m16n8k8 tf32 mma, cvt.rna.tf32.f32 operands.
//
// CC=8 / NSTAGE=5 / PFD=3 single-barrier pipeline:
//   per chunk: prefetch(ch+3) -> cp.async.wait_group 3 -> __syncthreads -> compute
// (stage overwritten at iter ch was last read at compute(ch-2), ordered by
//  barrier(ch-1) since NSTAGE = PFD+2).
//
// R13: all prefetch coordinates precomputed per-thread (no div/mod in the hot
// loop) and the 16-chunk loop fully unrolled so stage offsets are immediates
// (R12: alu=32%, issue=63% -- address math was eating issue slots).
//
// Epilogue: band-extract into a 41x132 smem tile (reuses ring smem), then
// coalesced float4 stores with .cs streaming hint.

#define C_TOT   128
#define W_DIM   256
#define H_DIM   192
#define B_DIM   8
#define NCTR    41
#define NT      256
#define CC      8
#define NCHUNK  (C_TOT / CC)       // 16
#define NSTAGE  5
#define PFD     3

#define A_PITCH 136                // 128 data + 8 pad   (136 mod 32 = 8)
#define B_PITCH 168                // 168 window floats  (168 mod 32 = 8)
#define BBLKS   42                 // float4 blocks per b channel row
#define STAGE_F (CC * (A_PITCH + B_PITCH))   // 2432 floats per stage
#define B_OFF   (CC * A_PITCH)               // 1088 floats
#define OUT_PITCH 132
#define RING_F  (NSTAGE * STAGE_F)           // 12160 floats
#define SMEM_BYTES (RING_F * 4)              // 48640 B (> 41*132*4 = 21648)

__device__ __forceinline__ void cpasync16(uint32_t dst, const void* src) {
    asm volatile("cp.async.cg.shared.global [%0], [%1], 16;\n" :: "r"(dst), "l"(src));
}
__device__ __forceinline__ void cp_commit() {
    asm volatile("cp.async.commit_group;\n");
}
__device__ __forceinline__ void cp_wait3() {
    asm volatile("cp.async.wait_group 3;\n" ::: "memory");
}
__device__ __forceinline__ uint32_t to_tf32(float f) {
    uint32_t u;
    asm("cvt.rna.tf32.f32 %0, %1;" : "=r"(u) : "f"(f));
    return u;
}
__device__ __forceinline__ void mma_tf32(float& d0, float& d1, float& d2, float& d3,
                                         uint32_t a0, uint32_t a1, uint32_t a2, uint32_t a3,
                                         uint32_t b0, uint32_t b1) {
    asm volatile("mma.sync.aligned.m16n8k8.row.col.f32.tf32.tf32.f32 "
                 "{%0,%1,%2,%3}, {%4,%5,%6,%7}, {%8,%9}, {%0,%1,%2,%3};\n"
                 : "+f"(d0), "+f"(d1), "+f"(d2), "+f"(d3)
                 : "r"(a0), "r"(a1), "r"(a2), "r"(a3), "r"(b0), "r"(b1));
}
__device__ __forceinline__ void stg_cs_v4(float* p, float x, float y, float z, float w) {
    asm volatile("st.global.cs.v4.f32 [%0], {%1, %2, %3, %4};\n"
                 :: "l"(p), "f"(x), "f"(y), "f"(z), "f"(w) : "memory");
}

__global__ __launch_bounds__(NT, 4)
void corr_kernel(const float* __restrict__ A,
                 const float* __restrict__ B,
                 float* __restrict__ O)
{
    extern __shared__ __align__(16) float sm[];

    const int bidx = blockIdx.x;
    const int row  = bidx >> 1;
    const int half = bidx & 1;
    const int bi   = row / H_DIM;
    const int h    = row - bi * H_DIM;
    const int hb   = half * 128;

    const int tid  = threadIdx.x;
    const int wid  = tid >> 5;
    const int lane = tid & 31;
    const int WL   = wid * 16;
    const int q    = lane & 3;
    const int r0   = lane >> 2;

    const size_t plane = (size_t)H_DIM * W_DIM;
    const float* Arow = A + ((size_t)bi * C_TOT * H_DIM + h) * W_DIM;
    const float* Brow = B + ((size_t)bi * C_TOT * H_DIM + h) * W_DIM;

    const uint32_t smb = (uint32_t)__cvta_generic_to_shared(sm);

    // ---- half 0: zero the 10 permanent pad blocks per b channel per stage ----
    if (half == 0) {
        for (int t = tid; t < NSTAGE * CC * 10; t += NT) {
            int st = t / (CC * 10);
            int u  = t - st * (CC * 10);
            int c  = u / 10;
            int l  = u - c * 10;
            float4* p = (float4*)(sm + st * STAGE_F + B_OFF + c * B_PITCH) + l;
            *p = make_float4(0.f, 0.f, 0.f, 0.f);
        }
    }

    float acc[7][4];
#pragma unroll
    for (int jt = 0; jt < 7; ++jt)
#pragma unroll
        for (int k = 0; k < 4; ++k) acc[jt][k] = 0.0f;

    // ---- precomputed prefetch coordinates (fixed per thread) ----
    const int bsrc_base = (hb >> 2) - 10;      // b source block of local block 0
    const size_t chstep = (size_t)CC * plane;

    // a copy: 8 ch x 32 blocks = 256 = NT
    const int ac = tid >> 5, ablk = tid & 31;
    const float*  asrc = Arow + (size_t)ac * plane + hb + ablk * 4;
    const uint32_t adst = smb + (ac * A_PITCH) * 4 + ablk * 16;

    // b copies: 8 ch x 42 blocks = 336 = 256 + 80
    const int c1 = tid / BBLKS, l1 = tid - c1 * BBLKS;
    const int g1 = bsrc_base + l1;
    const bool v1 = (g1 >= 0);
    const float*  bsrc1 = Brow + (size_t)c1 * plane + g1 * 4;
    const uint32_t bdst1 = smb + (B_OFF + c1 * B_PITCH) * 4 + l1 * 16;

    const int idx2 = tid + NT;                 // 256..511, valid < 336
    const int c2 = idx2 / BBLKS, l2 = idx2 - c2 * BBLKS;
    const int g2 = bsrc_base + l2;
    const bool v2 = (idx2 < CC * BBLKS) && (g2 >= 0);
    const float*  bsrc2 = Brow + (size_t)c2 * plane + g2 * 4;
    const uint32_t bdst2 = smb + (B_OFF + c2 * B_PITCH) * 4 + l2 * 16;

    auto prefetch = [&](int ch, uint32_t so) {
        const size_t off = (size_t)ch * chstep;
        cpasync16(adst + so, asrc + off);
        if (v1) cpasync16(bdst1 + so, bsrc1 + off);
        if (v2) cpasync16(bdst2 + so, bsrc2 + off);
        cp_commit();
    };

#pragma unroll
    for (int p = 0; p < PFD; ++p) prefetch(p, p * STAGE_F * 4);

#pragma unroll
    for (int ch = 0; ch < NCHUNK; ++ch) {
        // prefetch FIRST: stage (ch+PFD)%NSTAGE last read at compute(ch-2),
        // ordered by barrier(ch-1) since NSTAGE = PFD+2.
        if (ch + PFD < NCHUNK)
            prefetch(ch + PFD, ((ch + PFD) % NSTAGE) * STAGE_F * 4);
        else
            cp_commit();                       // empty group keeps FIFO invariant

        cp_wait3();        // this thread's copies for chunk ch complete
        __syncthreads();   // publish all threads' copies

        const float* as = sm + (ch % NSTAGE) * STAGE_F;   // immediate after unroll
        const float* bs = as + B_OFF;

        uint32_t a0 = to_tf32(as[q * A_PITCH + WL + r0]);
        uint32_t a1 = to_tf32(as[q * A_PITCH + WL + r0 + 8]);
        uint32_t a2 = to_tf32(as[(q + 4) * A_PITCH + WL + r0]);
        uint32_t a3 = to_tf32(as[(q + 4) * A_PITCH + WL + r0 + 8]);

#pragma unroll
        for (int jt = 0; jt < 7; ++jt) {
            int j = WL + jt * 8 + r0;
            uint32_t b0 = to_tf32(bs[q * B_PITCH + j]);
            uint32_t b1 = to_tf32(bs[(q + 4) * B_PITCH + j]);
            mma_tf32(acc[jt][0], acc[jt][1], acc[jt][2], acc[jt][3],
                     a0, a1, a2, a3, b0, b1);
        }
    }

    // ---- band extraction into smem: out_s[ctr][w_local] (reuses ring smem) ----
    __syncthreads();
#pragma unroll
    for (int jt = 0; jt < 7; ++jt) {
        int nb = jt * 8 + 2 * q;
        int ctr00 = nb - r0;
        int ctr10 = nb - (r0 + 8);
        if (ctr00 >= 0 && ctr00 <= 40)         sm[ctr00 * OUT_PITCH + WL + r0]           = acc[jt][0];
        if (ctr00 + 1 >= 0 && ctr00 + 1 <= 40) sm[(ctr00 + 1) * OUT_PITCH + WL + r0]     = acc[jt][1];
        if (ctr10 >= 0 && ctr10 <= 40)         sm[ctr10 * OUT_PITCH + WL + r0 + 8]       = acc[jt][2];
        if (ctr10 + 1 >= 0 && ctr10 + 1 <= 40) sm[(ctr10 + 1) * OUT_PITCH + WL + r0 + 8] = acc[jt][3];
    }
    __syncthreads();

    // ---- write-out: 41 x 32 float4, streaming (.cs) stores ----
    for (int idx = tid; idx < NCTR * 32; idx += NT) {
        int ctr = idx >> 5;
        int blk = idx & 31;
        const float* s = sm + ctr * OUT_PITCH + blk * 4;
        float* dst = O + (((size_t)bi * NCTR + ctr) * H_DIM + h) * W_DIM + hb + blk * 4;
        stg_cs_v4(dst, s[0], s[1], s[2], s[3]);
    }
}

extern "C" void kernel_launch(void* const* d_in, const int* in_sizes, int n_in,
                              void* d_out, int out_size)
{
    const float* a = (const float*)d_in[0];
    const float* b = (const float*)d_in[1];
    float* out = (float*)d_out;

    cudaFuncSetAttribute(corr_kernel,
                         cudaFuncAttributeMaxDynamicSharedMemorySize, SMEM_BYTES);

    dim3 grid(B_DIM * H_DIM * 2);   // 3072 CTAs, one per (batch, h, w-half)
    dim3 block(NT);
    corr_kernel<<<grid, block, SMEM_BYTES>>>(a, b, out);
}

// round 14
// speedup vs baseline: 1.1042x; 1.0202x over previous
#include <cuda_runtime.h>
#include <cstdint>

// Horizontal correlation cost volume via banded tf32 mma.sync GEMM.
// a,b: fp32 [B=8, C=128, H=192, W=256], D=40.
// out[bi, ctr, h, w] = sum_c a[bi,c,h,w] * bp[bi,c,h, ctr+w], bp left-padded by 40.
//
// 8 CTAs/SM x 128 threads: each CTA owns a QUARTER row (64 w's), grid=6144.
// Doubles independent barrier/cp.async domains per SM vs the half-row version
// (R11->R13 showed each domain doubling buys ~2-3 DRAM pts; L2 dedups the
// b-window overlap between co-scheduled neighbor CTAs so DRAM stays compulsory).
//
// 4 warps, warp = one 16-wide w tile; 7 n-tiles of 8 per warp (diagonal band).
// m16n8k8 tf32 mma, cvt.rna.tf32.f32 operands.
// CC=8 / NSTAGE=5 / PFD=3 single-barrier pipeline:
//   per chunk: prefetch(ch+3) -> cp.async.wait_group 3 -> __syncthreads -> compute
// (stage overwritten at iter ch last read at compute(ch-2), ordered by
//  barrier(ch-1) since NSTAGE = PFD+2). Prefetch coords precomputed; loop
// fully unrolled (stage offsets are immediates).
//
// Pitches: A_PITCH=72, B_PITCH=104, both == 8 (mod 32) -> fragment LDS banks
// 8q+r0+WL, conflict-free. Epilogue: band-extract into a 41x68 smem tile
// (reuses ring smem), then coalesced float4 .cs stores.

#define C_TOT   128
#define W_DIM   256
#define H_DIM   192
#define B_DIM   8
#define NCTR    41
#define NT      128
#define CC      8
#define NCHUNK  (C_TOT / CC)       // 16
#define NSTAGE  5
#define PFD     3

#define A_PITCH 72                 // 64 data + 8 pad    (72 mod 32 = 8)
#define B_PITCH 104                // 104 window floats  (104 mod 32 = 8)
#define BBLKS   26                 // float4 blocks per b channel row
#define STAGE_F (CC * (A_PITCH + B_PITCH))   // 1408 floats per stage
#define B_OFF   (CC * A_PITCH)               // 576 floats
#define OUT_PITCH 68                         // 68 mod 32 = 4
#define RING_F  (NSTAGE * STAGE_F)           // 7040 floats
#define SMEM_BYTES (RING_F * 4)              // 28160 B (> 41*68*4 = 11152)

__device__ __forceinline__ void cpasync16(uint32_t dst, const void* src) {
    asm volatile("cp.async.cg.shared.global [%0], [%1], 16;\n" :: "r"(dst), "l"(src));
}
__device__ __forceinline__ void cp_commit() {
    asm volatile("cp.async.commit_group;\n");
}
__device__ __forceinline__ void cp_wait3() {
    asm volatile("cp.async.wait_group 3;\n" ::: "memory");
}
__device__ __forceinline__ uint32_t to_tf32(float f) {
    uint32_t u;
    asm("cvt.rna.tf32.f32 %0, %1;" : "=r"(u) : "f"(f));
    return u;
}
__device__ __forceinline__ void mma_tf32(float& d0, float& d1, float& d2, float& d3,
                                         uint32_t a0, uint32_t a1, uint32_t a2, uint32_t a3,
                                         uint32_t b0, uint32_t b1) {
    asm volatile("mma.sync.aligned.m16n8k8.row.col.f32.tf32.tf32.f32 "
                 "{%0,%1,%2,%3}, {%4,%5,%6,%7}, {%8,%9}, {%0,%1,%2,%3};\n"
                 : "+f"(d0), "+f"(d1), "+f"(d2), "+f"(d3)
                 : "r"(a0), "r"(a1), "r"(a2), "r"(a3), "r"(b0), "r"(b1));
}
__device__ __forceinline__ void stg_cs_v4(float* p, float x, float y, float z, float w) {
    asm volatile("st.global.cs.v4.f32 [%0], {%1, %2, %3, %4};\n"
                 :: "l"(p), "f"(x), "f"(y), "f"(z), "f"(w) : "memory");
}

__global__ __launch_bounds__(NT, 8)
void corr_kernel(const float* __restrict__ A,
                 const float* __restrict__ B,
                 float* __restrict__ O)
{
    extern __shared__ __align__(16) float sm[];

    const int bidx = blockIdx.x;
    const int row  = bidx >> 2;                // (bi,h) row
    const int qtr  = bidx & 3;                 // which w-quarter
    const int bi   = row / H_DIM;
    const int h    = row - bi * H_DIM;
    const int hb   = qtr * 64;                 // w base of this CTA

    const int tid  = threadIdx.x;
    const int wid  = tid >> 5;                 // 0..3 -> local w tile
    const int lane = tid & 31;
    const int WL   = wid * 16;                 // local w base of this warp
    const int q    = lane & 3;
    const int r0   = lane >> 2;

    const size_t plane = (size_t)H_DIM * W_DIM;
    const float* Arow = A + ((size_t)bi * C_TOT * H_DIM + h) * W_DIM;
    const float* Brow = B + ((size_t)bi * C_TOT * H_DIM + h) * W_DIM;

    const uint32_t smb = (uint32_t)__cvta_generic_to_shared(sm);

    // ---- qtr 0: zero the 10 permanent pad blocks per b channel per stage ----
    if (qtr == 0) {
        for (int t = tid; t < NSTAGE * CC * 10; t += NT) {
            int st = t / (CC * 10);
            int u  = t - st * (CC * 10);
            int c  = u / 10;
            int l  = u - c * 10;
            float4* p = (float4*)(sm + st * STAGE_F + B_OFF + c * B_PITCH) + l;
            *p = make_float4(0.f, 0.f, 0.f, 0.f);
        }
    }

    float acc[7][4];
#pragma unroll
    for (int jt = 0; jt < 7; ++jt)
#pragma unroll
        for (int k = 0; k < 4; ++k) acc[jt][k] = 0.0f;

    // ---- precomputed prefetch coordinates (fixed per thread) ----
    const int bsrc_base = (hb >> 2) - 10;      // b source block of local block 0
    const size_t chstep = (size_t)CC * plane;

    // a copy: 8 ch x 16 blocks = 128 = NT
    const int ac = tid >> 4, ablk = tid & 15;
    const float*  asrc = Arow + (size_t)ac * plane + hb + ablk * 4;
    const uint32_t adst = smb + (ac * A_PITCH) * 4 + ablk * 16;

    // b copies: 8 ch x 26 blocks = 208 = 128 + 80
    const int c1 = tid / BBLKS, l1 = tid - c1 * BBLKS;
    const int g1 = bsrc_base + l1;
    const bool v1 = (tid < CC * BBLKS) && (g1 >= 0);   // tid<208 always true; keep form
    const float*  bsrc1 = Brow + (size_t)c1 * plane + g1 * 4;
    const uint32_t bdst1 = smb + (B_OFF + c1 * B_PITCH) * 4 + l1 * 16;

    const int idx2 = tid + NT;                 // 128..255, valid < 208
    const int c2 = idx2 / BBLKS, l2 = idx2 - c2 * BBLKS;
    const int g2 = bsrc_base + l2;
    const bool v2 = (idx2 < CC * BBLKS) && (g2 >= 0);
    const float*  bsrc2 = Brow + (size_t)c2 * plane + g2 * 4;
    const uint32_t bdst2 = smb + (B_OFF + c2 * B_PITCH) * 4 + l2 * 16;

    auto prefetch = [&](int ch, uint32_t so) {
        const size_t off = (size_t)ch * chstep;
        cpasync16(adst + so, asrc + off);
        if (v1) cpasync16(bdst1 + so, bsrc1 + off);
        if (v2) cpasync16(bdst2 + so, bsrc2 + off);
        cp_commit();
    };

#pragma unroll
    for (int p = 0; p < PFD; ++p) prefetch(p, p * STAGE_F * 4);

#pragma unroll
    for (int ch = 0; ch < NCHUNK; ++ch) {
        // prefetch FIRST: stage (ch+PFD)%NSTAGE last read at compute(ch-2),
        // ordered by barrier(ch-1) since NSTAGE = PFD+2.
        if (ch + PFD < NCHUNK)
            prefetch(ch + PFD, ((ch + PFD) % NSTAGE) * STAGE_F * 4);
        else
            cp_commit();                       // empty group keeps FIFO invariant

        cp_wait3();        // this thread's copies for chunk ch complete
        __syncthreads();   // publish all threads' copies

        const float* as = sm + (ch % NSTAGE) * STAGE_F;   // immediate after unroll
        const float* bs = as + B_OFF;

        uint32_t a0 = to_tf32(as[q * A_PITCH + WL + r0]);
        uint32_t a1 = to_tf32(as[q * A_PITCH + WL + r0 + 8]);
        uint32_t a2 = to_tf32(as[(q + 4) * A_PITCH + WL + r0]);
        uint32_t a3 = to_tf32(as[(q + 4) * A_PITCH + WL + r0 + 8]);

#pragma unroll
        for (int jt = 0; jt < 7; ++jt) {
            int j = WL + jt * 8 + r0;          // local bp index, max 103
            uint32_t b0 = to_tf32(bs[q * B_PITCH + j]);
            uint32_t b1 = to_tf32(bs[(q + 4) * B_PITCH + j]);
            mma_tf32(acc[jt][0], acc[jt][1], acc[jt][2], acc[jt][3],
                     a0, a1, a2, a3, b0, b1);
        }
    }

    // ---- band extraction into smem: out_s[ctr][w_local] (reuses ring smem) ----
    __syncthreads();
#pragma unroll
    for (int jt = 0; jt < 7; ++jt) {
        int nb = jt * 8 + 2 * q;
        int ctr00 = nb - r0;
        int ctr10 = nb - (r0 + 8);
        if (ctr00 >= 0 && ctr00 <= 40)         sm[ctr00 * OUT_PITCH + WL + r0]           = acc[jt][0];
        if (ctr00 + 1 >= 0 && ctr00 + 1 <= 40) sm[(ctr00 + 1) * OUT_PITCH + WL + r0]     = acc[jt][1];
        if (ctr10 >= 0 && ctr10 <= 40)         sm[ctr10 * OUT_PITCH + WL + r0 + 8]       = acc[jt][2];
        if (ctr10 + 1 >= 0 && ctr10 + 1 <= 40) sm[(ctr10 + 1) * OUT_PITCH + WL + r0 + 8] = acc[jt][3];
    }
    __syncthreads();

    // ---- write-out: 41 x 16 float4, streaming (.cs) stores ----
    for (int idx = tid; idx < NCTR * 16; idx += NT) {
        int ctr = idx >> 4;
        int blk = idx & 15;
        const float* s = sm + ctr * OUT_PITCH + blk * 4;
        float* dst = O + (((size_t)bi * NCTR + ctr) * H_DIM + h) * W_DIM + hb + blk * 4;
        stg_cs_v4(dst, s[0], s[1], s[2], s[3]);
    }
}

extern "C" void kernel_launch(void* const* d_in, const int* in_sizes, int n_in,
                              void* d_out, int out_size)
{
    const float* a = (const float*)d_in[0];
    const float* b = (const float*)d_in[1];
    float* out = (float*)d_out;

    cudaFuncSetAttribute(corr_kernel,
                         cudaFuncAttributeMaxDynamicSharedMemorySize, SMEM_BYTES);

    dim3 grid(B_DIM * H_DIM * 4);   // 6144 CTAs, one per (batch, h, w-quarter)
    dim3 block(NT);
    corr_kernel<<<grid, block, SMEM_BYTES>>>(a, b, out);
}